// round 3
// baseline (speedup 1.0000x reference)
#include <cuda_runtime.h>
#include <math.h>
#include <float.h>

#define BS 32
#define NQ 300
#define NC 2001
#define NT 25

// Scratch cost matrix, stored transposed as [b][t][q] (the LSAP works on C = cost^T).
// float32 (matches reference: cost computed in f32, then widened to f64 — widening is exact).
__device__ float g_cost[BS * NT * NQ];

// ---------------------------------------------------------------------------
// Phase A: softmax over classes + gather target-class probs -> -prob cost.
// One warp per (b, q). Coalesced strided reads over the 2001 classes.
// ---------------------------------------------------------------------------
__global__ void cost_kernel(const float* __restrict__ logits,
                            const int* __restrict__ targets) {
    const unsigned FULL = 0xffffffffu;
    int gwarp = (blockIdx.x * blockDim.x + threadIdx.x) >> 5;
    int lane  = threadIdx.x & 31;
    if (gwarp >= BS * NQ) return;
    int b = gwarp / NQ;
    int q = gwarp % NQ;

    const float* row = logits + ((size_t)b * NQ + q) * NC;

    // max over classes
    float m = -FLT_MAX;
    for (int c = lane; c < NC; c += 32) m = fmaxf(m, row[c]);
    #pragma unroll
    for (int o = 16; o; o >>= 1) m = fmaxf(m, __shfl_xor_sync(FULL, m, o));

    // sum of exp(x - max)
    float s = 0.f;
    for (int c = lane; c < NC; c += 32) s += expf(row[c] - m);
    #pragma unroll
    for (int o = 16; o; o >>= 1) s += __shfl_xor_sync(FULL, s, o);

    // lanes 0..NT-1 gather target-class prob, write -prob transposed
    if (lane < NT) {
        int cls = targets[b * NT + lane];
        float p = expf(row[cls] - m) / s;
        g_cost[((size_t)b * NT + lane) * NQ + q] = -p;
    }
}

// ---------------------------------------------------------------------------
// Phase B: Jonker-Volgenant shortest augmenting path LSAP, one warp per batch.
// Exactly mirrors the reference _lsa() including argmin tie-breaking
// (first minimum in ascending column order) and float64 dual arithmetic.
// ---------------------------------------------------------------------------
__global__ void lsap_kernel(float* __restrict__ out) {
    const unsigned FULL = 0xffffffffu;
    int b    = blockIdx.x;
    int lane = threadIdx.x;  // blockDim.x == 32

    __shared__ float  C[NT * NQ];         // 30000 B
    __shared__ double v[NQ];
    __shared__ double shortest[NQ];
    __shared__ double u[NT];
    __shared__ int    path[NQ];
    __shared__ int    row4col[NQ];
    __shared__ int    col4row[NT];
    __shared__ unsigned char SC[NQ];
    __shared__ int    sr[NT];             // rows in alternating tree
    __shared__ int    s_i, s_sink, s_nsr;
    __shared__ double s_minVal;

    // load cost tile + init persistent state
    const float* src = g_cost + (size_t)b * NT * NQ;
    for (int k = lane; k < NT * NQ; k += 32) C[k] = src[k];
    for (int j = lane; j < NQ; j += 32) { v[j] = 0.0; row4col[j] = -1; }
    if (lane < NT) { u[lane] = 0.0; col4row[lane] = -1; }
    __syncwarp();

    for (int cur = 0; cur < NT; cur++) {
        for (int j = lane; j < NQ; j += 32) {
            shortest[j] = DBL_MAX;
            path[j] = -1;
            SC[j] = 0;
        }
        if (lane == 0) { s_i = cur; s_minVal = 0.0; s_sink = -1; s_nsr = 0; }
        __syncwarp();

        // shortest augmenting path search
        while (true) {
            int    i      = s_i;
            double minVal = s_minVal;
            if (lane == 0) sr[s_nsr++] = i;
            double ui = u[i];
            const float* Crow = C + i * NQ;

            // relax + local argmin over this lane's columns (ascending j, strict <
            // keeps the FIRST minimum, matching np.argmin tie-break)
            double best  = DBL_MAX;
            int    bestj = -1;
            for (int j = lane; j < NQ; j += 32) {
                if (!SC[j]) {
                    double d = minVal + (double)Crow[j] - ui - v[j];
                    if (d < shortest[j]) { shortest[j] = d; path[j] = i; }
                    double sj = shortest[j];
                    if (sj < best) { best = sj; bestj = j; }
                }
            }
            // warp argmin, lexicographic (val, idx)
            #pragma unroll
            for (int o = 16; o; o >>= 1) {
                double ov = __shfl_down_sync(FULL, best, o);
                int    oj = __shfl_down_sync(FULL, bestj, o);
                if (oj != -1 && (ov < best || (ov == best && (bestj == -1 || oj < bestj)))) {
                    best = ov; bestj = oj;
                }
            }
            if (lane == 0) {
                s_minVal = best;
                SC[bestj] = 1;
                if (row4col[bestj] == -1) s_sink = bestj;
                else                      s_i = row4col[bestj];
            }
            __syncwarp();
            if (s_sink != -1) break;
        }

        double minVal = s_minVal;
        int    sink   = s_sink;

        // dual updates: u (serial, <=25 rows) and v (parallel over SC columns)
        if (lane == 0) {
            u[cur] += minVal;
            for (int k = 0; k < s_nsr; k++) {
                int ir = sr[k];
                if (ir != cur) u[ir] += minVal - shortest[col4row[ir]];
            }
        }
        for (int j = lane; j < NQ; j += 32)
            if (SC[j]) v[j] -= minVal - shortest[j];
        __syncwarp();

        // augment along the found path (serial, short)
        if (lane == 0) {
            int j = sink;
            while (true) {
                int i = path[j];
                row4col[j] = i;
                int nxt = col4row[i];
                col4row[i] = j;
                j = nxt;
                if (i == cur) break;
            }
        }
        __syncwarp();
    }

    // order = stable argsort(col4row); values distinct -> rank by counting.
    // row_inds[k] = col4row[order[k]], col_inds[k] = order[k].
    // Output graded as float32: small integers are exactly representable.
    if (lane < NT) {
        int myv = col4row[lane];
        int pos = 0;
        #pragma unroll
        for (int t = 0; t < NT; t++) pos += (col4row[t] < myv) ? 1 : 0;
        out[b * NT + pos]            = (float)myv;   // row_inds
        out[BS * NT + b * NT + pos]  = (float)lane;  // col_inds
    }
}

// ---------------------------------------------------------------------------
extern "C" void kernel_launch(void* const* d_in, const int* in_sizes, int n_in,
                              void* d_out, int out_size) {
    const float* logits  = (const float*)d_in[0];   // [32, 300, 2001] f32
    const int*   targets = (const int*)d_in[1];     // [32, 25] i32
    float*       out     = (float*)d_out;           // [2, 32, 25] graded as f32

    // Phase A: 9600 warps, 8 warps/block
    int total_warps = BS * NQ;
    int threads = 256;
    int blocks = (total_warps * 32 + threads - 1) / threads;
    cost_kernel<<<blocks, threads>>>(logits, targets);

    // Phase B: one warp per batch element
    lsap_kernel<<<BS, 32>>>(out);
}

// round 5
// speedup vs baseline: 3.0419x; 3.0419x over previous
#include <cuda_runtime.h>
#include <math.h>
#include <float.h>

#define BS 32
#define NQ 300
#define NC 2001
#define NT 25
#define NSLOT 10   // ceil(300/32)

// Scratch cost matrix, stored transposed as [b][t][q] (the LSAP works on C = cost^T).
__device__ float g_cost[BS * NT * NQ];

// ---------------------------------------------------------------------------
// Phase A: softmax over classes + gather target-class probs -> -prob cost.
// One warp per (b, q). Coalesced strided reads over the 2001 classes.
// ---------------------------------------------------------------------------
__global__ void cost_kernel(const float* __restrict__ logits,
                            const int* __restrict__ targets) {
    const unsigned FULL = 0xffffffffu;
    int gwarp = (blockIdx.x * blockDim.x + threadIdx.x) >> 5;
    int lane  = threadIdx.x & 31;
    if (gwarp >= BS * NQ) return;
    int b = gwarp / NQ;
    int q = gwarp % NQ;

    const float* row = logits + ((size_t)b * NQ + q) * NC;

    float m = -FLT_MAX;
    for (int c = lane; c < NC; c += 32) m = fmaxf(m, row[c]);
    #pragma unroll
    for (int o = 16; o; o >>= 1) m = fmaxf(m, __shfl_xor_sync(FULL, m, o));

    float s = 0.f;
    for (int c = lane; c < NC; c += 32) s += expf(row[c] - m);
    #pragma unroll
    for (int o = 16; o; o >>= 1) s += __shfl_xor_sync(FULL, s, o);

    if (lane < NT) {
        int cls = targets[b * NT + lane];
        float p = expf(row[cls] - m) / s;
        g_cost[((size_t)b * NT + lane) * NQ + q] = -p;
    }
}

// ---------------------------------------------------------------------------
// Phase B: JV shortest-augmenting-path LSAP, one warp per batch.
// fp32, register-resident per-column state (shortest / v / SC), redux argmin.
// Column j is owned by lane (j & 31), register slot (j >> 5).
// ---------------------------------------------------------------------------
__global__ void lsap_kernel(float* __restrict__ out) {
    const unsigned FULL = 0xffffffffu;
    int b    = blockIdx.x;
    int lane = threadIdx.x;  // blockDim.x == 32

    __shared__ float C[NT * NQ];     // cost rows (row-major by target i)
    __shared__ float u[NT];          // row duals
    __shared__ int   path[NQ];       // predecessor row per column
    __shared__ int   row4col[NQ];
    __shared__ int   col4row[NT];
    __shared__ int   sr[NT];         // rows in the alternating tree
    __shared__ float disc[NT];       // shortest[col4row[sr[k]]] at discovery

    const float* src = g_cost + (size_t)b * NT * NQ;
    for (int k = lane; k < NT * NQ; k += 32) C[k] = src[k];
    for (int j = lane; j < NQ; j += 32) row4col[j] = -1;
    if (lane < NT) { u[lane] = 0.f; col4row[lane] = -1; }

    float vv[NSLOT];
    #pragma unroll
    for (int s = 0; s < NSLOT; s++) vv[s] = 0.f;
    // slot 9 covers j = 288 + lane; invalid when j >= 300 (lane >= 12)
    const unsigned invmask = (lane >= 12) ? (1u << 9) : 0u;
    __syncwarp();

    for (int cur = 0; cur < NT; cur++) {
        float sh[NSLOT];
        #pragma unroll
        for (int s = 0; s < NSLOT; s++) sh[s] = FLT_MAX;
        unsigned scm = invmask;      // SC bitmask (per-lane slots)
        int   i      = cur;
        float minVal = 0.f;
        int   nsr    = 0;
        int   sink   = -1;

        while (true) {
            if (lane == 0) { sr[nsr] = i; disc[nsr] = minVal; }
            nsr++;

            float a = minVal - u[i];           // broadcast LDS
            const float* Crow = &C[i * NQ];

            // relax + local first-min (ascending slot == ascending j)
            float bestv = FLT_MAX;
            int   bests = -1;
            #pragma unroll
            for (int s = 0; s < NSLOT; s++) {
                if (!((scm >> s) & 1u)) {
                    float d = (Crow[s * 32 + lane] + a) - vv[s];
                    if (d < sh[s]) { sh[s] = d; path[s * 32 + lane] = i; }
                    if (sh[s] < bestv) { bestv = sh[s]; bests = s; }
                }
            }

            // warp argmin via monotonic float->uint key, then min column index
            unsigned key;
            if (bests < 0) key = 0xFFFFFFFFu;
            else {
                unsigned bb = __float_as_uint(bestv);
                key = (bb & 0x80000000u) ? ~bb : (bb | 0x80000000u);
            }
            unsigned minkey = __reduce_min_sync(FULL, key);
            unsigned myj = (key == minkey && bests >= 0)
                               ? (unsigned)(bests * 32 + lane) : 0xFFFFFFFFu;
            int bestj = (int)__reduce_min_sync(FULL, myj);

            unsigned nb = (minkey & 0x80000000u) ? (minkey ^ 0x80000000u) : ~minkey;
            minVal = __uint_as_float(nb);

            if (lane == (bestj & 31)) scm |= 1u << (bestj >> 5);

            int rc = row4col[bestj];           // broadcast LDS
            if (rc == -1) { sink = bestj; break; }
            i = rc;
        }

        // v dual update: only columns scanned THIS round (scm minus invalid);
        // for those, sh[s] froze at its discovery value == shortest[j].
        #pragma unroll
        for (int s = 0; s < NSLOT; s++) {
            if (((scm >> s) & 1u) && !((invmask >> s) & 1u))
                vv[s] -= minVal - sh[s];
        }

        if (lane == 0) {
            // u dual updates (sr[0] == cur)
            u[cur] += minVal;
            for (int k = 1; k < nsr; k++) u[sr[k]] += minVal - disc[k];
            // augment along the path
            int j = sink;
            while (true) {
                int i2 = path[j];
                row4col[j] = i2;
                int nxt = col4row[i2];
                col4row[i2] = j;
                j = nxt;
                if (i2 == cur) break;
            }
        }
        __syncwarp();
    }

    // stable argsort of distinct ints by rank counting; outputs graded as f32.
    if (lane < NT) {
        int myv = col4row[lane];
        int pos = 0;
        #pragma unroll
        for (int t = 0; t < NT; t++) pos += (col4row[t] < myv) ? 1 : 0;
        out[b * NT + pos]           = (float)myv;   // row_inds
        out[BS * NT + b * NT + pos] = (float)lane;  // col_inds
    }
}

// ---------------------------------------------------------------------------
extern "C" void kernel_launch(void* const* d_in, const int* in_sizes, int n_in,
                              void* d_out, int out_size) {
    const float* logits  = (const float*)d_in[0];   // [32, 300, 2001] f32
    const int*   targets = (const int*)d_in[1];     // [32, 25] i32
    float*       out     = (float*)d_out;           // [2, 32, 25] graded as f32

    int total_warps = BS * NQ;
    int threads = 256;
    int blocks = (total_warps * 32 + threads - 1) / threads;
    cost_kernel<<<blocks, threads>>>(logits, targets);

    lsap_kernel<<<BS, 32>>>(out);
}

// round 8
// speedup vs baseline: 5.0651x; 1.6651x over previous
#include <cuda_runtime.h>
#include <math.h>
#include <float.h>

#define BS 32
#define NQ 300
#define NC 2001
#define NT 25

// Scratch cost matrix, stored transposed as [b][t][q].
__device__ float g_cost[BS * NT * NQ];

// ---------------------------------------------------------------------------
// Phase A: softmax over classes + gather target-class probs -> -prob cost.
// ---------------------------------------------------------------------------
__global__ void cost_kernel(const float* __restrict__ logits,
                            const int* __restrict__ targets) {
    const unsigned FULL = 0xffffffffu;
    int gwarp = (blockIdx.x * blockDim.x + threadIdx.x) >> 5;
    int lane  = threadIdx.x & 31;
    if (gwarp >= BS * NQ) return;
    int b = gwarp / NQ;
    int q = gwarp % NQ;

    const float* row = logits + ((size_t)b * NQ + q) * NC;

    float m = -FLT_MAX;
    for (int c = lane; c < NC; c += 32) m = fmaxf(m, row[c]);
    #pragma unroll
    for (int o = 16; o; o >>= 1) m = fmaxf(m, __shfl_xor_sync(FULL, m, o));

    float s = 0.f;
    for (int c = lane; c < NC; c += 32) s += expf(row[c] - m);
    #pragma unroll
    for (int o = 16; o; o >>= 1) s += __shfl_xor_sync(FULL, s, o);

    if (lane < NT) {
        int cls = targets[b * NT + lane];
        float p = expf(row[cls] - m) / s;
        g_cost[((size_t)b * NT + lane) * NQ + q] = -p;
    }
}

// monotonic float<->uint order-preserving transform
__device__ __forceinline__ unsigned fkey(float x) {
    unsigned v = __float_as_uint(x);
    return (v & 0x80000000u) ? ~v : (v | 0x80000000u);
}
__device__ __forceinline__ float funkey(unsigned k) {
    unsigned v = (k & 0x80000000u) ? (k ^ 0x80000000u) : ~k;
    return __uint_as_float(v);
}

// ---------------------------------------------------------------------------
// Phase B: JV LSAP, one warp per batch. Lane l<25 owns columns [12l, 12l+12).
// Fast path: searches whose first pop lands on an unassigned column are exactly
// one relax + assignment. Conflicts fall back to the general loop using R5's
// association (C + (minVal - u)) - v, which computes minVal-u exactly and thus
// reproduces the reference's float64 tie structure for duplicate-class rows.
// ---------------------------------------------------------------------------
__global__ void lsap_kernel(float* __restrict__ out) {
    const unsigned FULL = 0xffffffffu;
    int b    = blockIdx.x;
    int lane = threadIdx.x;   // blockDim.x == 32

    __shared__ alignas(16) float C[NT * NQ];
    __shared__ alignas(16) int   path[NQ];
    __shared__ float u[NT];
    __shared__ int   row4col[NQ];
    __shared__ int   col4row[NT];
    __shared__ int   sr[NT];
    __shared__ float disc[NT];

    {   // vectorized cost load (7500 floats = 1875 float4, both sides 16B aligned)
        const float4* src = (const float4*)(g_cost + (size_t)b * NT * NQ);
        float4* dst = (float4*)C;
        for (int k = lane; k < (NT * NQ) / 4; k += 32) dst[k] = src[k];
    }
    for (int j = lane; j < NQ; j += 32) row4col[j] = -1;
    if (lane < NT) { u[lane] = 0.f; col4row[lane] = -1; }
    __syncwarp();

    const bool active = (lane < 25);
    float vv[12];
    #pragma unroll
    for (int s = 0; s < 12; s++) vv[s] = 0.f;

    for (int cur = 0; cur < NT; cur++) {
        // ---- iteration 1 (u[cur]==0, minVal==0): shortest[j] = C[cur][j] - v[j]
        float d[12];
        float bv = FLT_MAX; int bs = 0;
        if (active) {
            const float4* Crow = (const float4*)&C[cur * NQ + 12 * lane];
            float4 c0 = Crow[0], c1 = Crow[1], c2 = Crow[2];
            d[0]=c0.x-vv[0];  d[1]=c0.y-vv[1];  d[2]=c0.z-vv[2];  d[3]=c0.w-vv[3];
            d[4]=c1.x-vv[4];  d[5]=c1.y-vv[5];  d[6]=c1.z-vv[6];  d[7]=c1.w-vv[7];
            d[8]=c2.x-vv[8];  d[9]=c2.y-vv[9];  d[10]=c2.z-vv[10]; d[11]=c2.w-vv[11];
            // first-min select tree (ties -> lower slot == lower j)
            float v6[6]; int s6[6];
            #pragma unroll
            for (int k = 0; k < 6; k++) {
                bool p = d[2*k+1] < d[2*k];
                v6[k] = p ? d[2*k+1] : d[2*k];
                s6[k] = p ? 2*k+1 : 2*k;
            }
            float v3[3]; int s3[3];
            #pragma unroll
            for (int k = 0; k < 3; k++) {
                bool p = v6[2*k+1] < v6[2*k];
                v3[k] = p ? v6[2*k+1] : v6[2*k];
                s3[k] = p ? s6[2*k+1] : s6[2*k];
            }
            bool p0 = v3[1] < v3[0];
            float vx = p0 ? v3[1] : v3[0];
            int   sx = p0 ? s3[1] : s3[0];
            bool p1 = v3[2] < vx;
            bv = p1 ? v3[2] : vx;
            bs = p1 ? s3[2] : sx;
        }
        unsigned key    = active ? fkey(bv) : 0xFFFFFFFFu;
        unsigned minkey = __reduce_min_sync(FULL, key);
        unsigned myj    = (active && key == minkey) ? (unsigned)(12*lane + bs)
                                                    : 0xFFFFFFFFu;
        int   bestj  = (int)__reduce_min_sync(FULL, myj);
        float minVal = funkey(minkey);
        int   rc     = row4col[bestj];

        if (rc == -1) {
            // single-pop search: v[sink] unchanged, u[cur] = minVal, assign.
            if (lane == 0) {
                u[cur] = minVal;
                row4col[bestj] = cur;
                col4row[cur]   = bestj;
            }
            __syncwarp();
            continue;
        }

        // ---- conflict: continue the exact general JV search -------------
        float sh[12];
        #pragma unroll
        for (int s = 0; s < 12; s++) sh[s] = d[s];
        unsigned scm = active ? 0u : 0xFFFu;   // scanned-column mask per lane
        if (active) {                          // path[j] = cur for all j (iter-1 improved all)
            int4 pc = make_int4(cur, cur, cur, cur);
            int4* pp = (int4*)&path[12 * lane];
            pp[0] = pc; pp[1] = pc; pp[2] = pc;
        }
        if (lane == bestj / 12) scm |= 1u << (bestj % 12);
        if (lane == 0) { sr[0] = cur; disc[0] = 0.f; }
        int nsr  = 1;
        int i    = rc;
        int sink = -1;

        while (true) {
            if (lane == 0) { sr[nsr] = i; disc[nsr] = minVal; }
            nsr++;
            float ui  = u[i];
            float am  = minVal - ui;   // exact 0 for duplicate-row conflicts
            float bv2 = FLT_MAX; int bs2 = -1;
            if (active) {
                const float4* Crow = (const float4*)&C[i * NQ + 12 * lane];
                float4 c0 = Crow[0], c1 = Crow[1], c2 = Crow[2];
                float cc[12] = {c0.x,c0.y,c0.z,c0.w, c1.x,c1.y,c1.z,c1.w,
                                c2.x,c2.y,c2.z,c2.w};
                #pragma unroll
                for (int s = 0; s < 12; s++) {
                    if (!((scm >> s) & 1u)) {
                        // R5 association: (C + (minVal - u)) - v
                        float dd = (cc[s] + am) - vv[s];
                        if (dd < sh[s]) { sh[s] = dd; path[12*lane + s] = i; }
                        if (sh[s] < bv2) { bv2 = sh[s]; bs2 = s; }
                    }
                }
            }
            unsigned k2 = (bs2 >= 0) ? fkey(bv2) : 0xFFFFFFFFu;
            unsigned mk = __reduce_min_sync(FULL, k2);
            unsigned mj = (k2 == mk && bs2 >= 0) ? (unsigned)(12*lane + bs2)
                                                 : 0xFFFFFFFFu;
            int bj = (int)__reduce_min_sync(FULL, mj);
            minVal = funkey(mk);
            if (lane == bj / 12) scm |= 1u << (bj % 12);
            int r2 = row4col[bj];
            if (r2 == -1) { sink = bj; break; }
            i = r2;
        }

        // v duals: scanned columns froze sh at their pop value == shortest[j]
        if (active) {
            #pragma unroll
            for (int s = 0; s < 12; s++)
                if ((scm >> s) & 1u) vv[s] -= minVal - sh[s];
        }
        __syncwarp();
        if (lane == 0) {
            u[cur] += minVal;
            for (int k = 1; k < nsr; k++) u[sr[k]] += minVal - disc[k];
            int j = sink;
            while (true) {
                int i2 = path[j];
                row4col[j] = i2;
                int nxt = col4row[i2];
                col4row[i2] = j;
                j = nxt;
                if (i2 == cur) break;
            }
        }
        __syncwarp();
    }

    // stable argsort of distinct ints by rank counting; graded as float32.
    if (lane < NT) {
        int myv = col4row[lane];
        int pos = 0;
        #pragma unroll
        for (int t = 0; t < NT; t++) pos += (col4row[t] < myv) ? 1 : 0;
        out[b * NT + pos]           = (float)myv;   // row_inds
        out[BS * NT + b * NT + pos] = (float)lane;  // col_inds
    }
}

// ---------------------------------------------------------------------------
extern "C" void kernel_launch(void* const* d_in, const int* in_sizes, int n_in,
                              void* d_out, int out_size) {
    const float* logits  = (const float*)d_in[0];   // [32, 300, 2001] f32
    const int*   targets = (const int*)d_in[1];     // [32, 25] i32
    float*       out     = (float*)d_out;           // [2, 32, 25] graded as f32

    int total_warps = BS * NQ;
    int threads = 256;
    int blocks = (total_warps * 32 + threads - 1) / threads;
    cost_kernel<<<blocks, threads>>>(logits, targets);

    lsap_kernel<<<BS, 32>>>(out);
}